// round 14
// baseline (speedup 1.0000x reference)
#include <cuda_runtime.h>
#include <math.h>

// Problem constants
#define NTOKS 4096   // B*T
#define DIMV  512
#define QDV   2048   // 2*H*DH
#define HV    8
#define DHV   128
#define NKV   256
#define KKV   16

typedef unsigned long long ull;

// packed fp32x2 FMA (sm_103a FFMA2) — bit-exact fp32 per lane
#define FMA2(d, a, b) \
    asm("fma.rn.f32x2 %0, %1, %2, %0;" : "+l"(d) : "l"(a), "l"(b))
#define PACKDUP(out, x) \
    asm("mov.b64 %0, {%1, %1};" : "=l"(out) : "r"(__float_as_uint(x)))
#define UNPACK2(lo, hi, in) \
    asm("mov.b64 {%0, %1}, %2;" : "=r"(lo), "=r"(hi) : "l"(in))

// Scratch (allocation-free rule: __device__ globals)
__device__ __align__(16) float g_q[NTOKS * QDV];          // LN'd projected q
__device__ __align__(16) float g_attn[NTOKS * HV * KKV];  // softmax weights
__device__ __align__(16) int   g_vidx[NTOKS * HV * KKV];  // value row indices

// Stage-2 candidate tables: (i,j) with (i+1)(j+1) <= 16 — 50 candidates,
// provably a superset of the top-16 of sx[i]+sy[j] with sx,sy sorted desc
// (exact under the reference's lower-flattened-index tie-break).
__device__ __constant__ int c_ci[64] = {
    0,0,0,0,0,0,0,0,0,0,0,0,0,0,0,0,
    1,1,1,1,1,1,1,1,
    2,2,2,2,2,
    3,3,3,3,
    4,4,4,
    5,5, 6,6, 7,7,
    8,9,10,11,12,13,14,15,
    0,0,0,0,0,0,0,0,0,0,0,0,0,0};
__device__ __constant__ int c_cj[64] = {
    0,1,2,3,4,5,6,7,8,9,10,11,12,13,14,15,
    0,1,2,3,4,5,6,7,
    0,1,2,3,4,
    0,1,2,3,
    0,1,2,
    0,1, 0,1, 0,1,
    0,0,0,0,0,0,0,0,
    0,0,0,0,0,0,0,0,0,0,0,0,0,0};

// ---------------------------------------------------------------------------
// K1 (+fused LN): VERBATIM round 13 (541.2us). q = LN(x @ Wq^T), FFMA2,
// bit-exact sequential-k chain, register-prefetch pipeline, k2-layout LN.
// ---------------------------------------------------------------------------
__global__ __launch_bounds__(256) void k1_gemm_ln(const float* __restrict__ X,
                                                  const float* __restrict__ W,
                                                  const float* __restrict__ gamma,
                                                  const float* __restrict__ beta)
{
    __shared__ float As[16][68];    // [k][m] 64 rows + pad
    __shared__ float Bs[16][132];   // [k][n] 128 rows + pad

    const int tid = threadIdx.x;
    const int tx = tid & 31;       // n-group: cols tx*4..tx*4+3
    const int ty = tid >> 5;       // m-group (warp id)
    const int m0 = blockIdx.x * 64;
    const int n0 = blockIdx.y * 128;   // exactly one (p,h) head slice

    ull acc[4][4];                 // [row-pair][col]
#pragma unroll
    for (int ip = 0; ip < 4; ip++)
#pragma unroll
        for (int j = 0; j < 4; j++) acc[ip][j] = 0ULL;

    const int arow = tid >> 2;          // 0..63
    const int akc  = (tid & 3) << 2;    // 0,4,8,12
    const int brow0 = tid >> 2;         // 0..63   (q=0)
    const int brow1 = 64 + (tid >> 2);  // 64..127 (q=1)

    const float* Abase = X + (size_t)(m0 + arow) * DIMV + akc;
    const float* Bbase0 = W + (size_t)(n0 + brow0) * DIMV + akc;
    const float* Bbase1 = W + (size_t)(n0 + brow1) * DIMV + akc;

    // prologue: prefetch tile kt=0
    float4 pa  = *(const float4*)(Abase);
    float4 pb0 = *(const float4*)(Bbase0);
    float4 pb1 = *(const float4*)(Bbase1);

    for (int kt = 0; kt < DIMV; kt += 16) {
        As[akc + 0][arow] = pa.x; As[akc + 1][arow] = pa.y;
        As[akc + 2][arow] = pa.z; As[akc + 3][arow] = pa.w;
        Bs[akc + 0][brow0] = pb0.x; Bs[akc + 1][brow0] = pb0.y;
        Bs[akc + 2][brow0] = pb0.z; Bs[akc + 3][brow0] = pb0.w;
        Bs[akc + 0][brow1] = pb1.x; Bs[akc + 1][brow1] = pb1.y;
        Bs[akc + 2][brow1] = pb1.z; Bs[akc + 3][brow1] = pb1.w;
        __syncthreads();

        if (kt + 16 < DIMV) {
            pa  = *(const float4*)(Abase + kt + 16);
            pb0 = *(const float4*)(Bbase0 + kt + 16);
            pb1 = *(const float4*)(Bbase1 + kt + 16);
        }

#pragma unroll 4
        for (int k = 0; k < 16; k++) {
            ulonglong2 a01 = *(const ulonglong2*)&As[k][ty * 4];
            ulonglong2 a23 = *(const ulonglong2*)&As[k][32 + ty * 4];
            ull av[4] = {a01.x, a01.y, a23.x, a23.y};
            float4 b = *(const float4*)&Bs[k][tx * 4];
            ull bd[4];
            PACKDUP(bd[0], b.x); PACKDUP(bd[1], b.y);
            PACKDUP(bd[2], b.z); PACKDUP(bd[3], b.w);
#pragma unroll
            for (int ip = 0; ip < 4; ip++)
#pragma unroll
                for (int j = 0; j < 4; j++)
                    FMA2(acc[ip][j], av[ip], bd[j]);
        }
        __syncthreads();
    }

    // epilogue: LN per row (exact k2 layout + reduction tree), then store.
    float4 g4 = *(const float4*)(gamma + tx * 4);
    float4 b4 = *(const float4*)(beta + tx * 4);

#pragma unroll
    for (int ip = 0; ip < 4; ip++) {
#pragma unroll
        for (int e = 0; e < 2; e++) {
            int row = (ip >> 1) * 32 + ty * 4 + (ip & 1) * 2 + e;
            float4 v;
            {
                unsigned lo, hi;
                UNPACK2(lo, hi, acc[ip][0]); v.x = __uint_as_float(e ? hi : lo);
                UNPACK2(lo, hi, acc[ip][1]); v.y = __uint_as_float(e ? hi : lo);
                UNPACK2(lo, hi, acc[ip][2]); v.z = __uint_as_float(e ? hi : lo);
                UNPACK2(lo, hi, acc[ip][3]); v.w = __uint_as_float(e ? hi : lo);
            }
            float s = v.x + v.y + v.z + v.w;
#pragma unroll
            for (int o = 16; o; o >>= 1) s += __shfl_xor_sync(0xffffffffu, s, o);
            float mu = s * (1.0f / 128.0f);

            float dx = v.x - mu, dy = v.y - mu, dz = v.z - mu, dw = v.w - mu;
            float ss = dx * dx + dy * dy + dz * dz + dw * dw;
#pragma unroll
            for (int o = 16; o; o >>= 1) ss += __shfl_xor_sync(0xffffffffu, ss, o);
            float inv = rsqrtf(ss * (1.0f / 128.0f) + 1e-5f);

            v.x = dx * inv * g4.x + b4.x;
            v.y = dy * inv * g4.y + b4.y;
            v.z = dz * inv * g4.z + b4.z;
            v.w = dw * inv * g4.w + b4.w;
            float* dst = g_q + (size_t)(m0 + row) * QDV + n0 + tx * 4;
            *(float4*)dst = v;
        }
    }
}

// ---------------------------------------------------------------------------
// K3 (fused K4): dots with reduced issue count — q pre-duplicated in smem
// (LDS.64 broadcast replaces LDS.32+MOV64) and kv as 2x LDS.128 over
// consecutive-key runs (thread keys: 4tx..4tx+3 and 128+4tx..128+4tx+3).
// Per-(token,key) FMA chains keep identical operands and k-order (bit-exact);
// stage-1 slot->index map updated to match (still increasing in s, exact
// invalidation) so tie-break semantics are unchanged. Selection ILP-4,
// pruned stage-2, softmax — verbatim round 13 logic.
// ---------------------------------------------------------------------------
__global__ __launch_bounds__(256, 3) void k3_fused(const float* __restrict__ keys)
{
    __shared__ float qsd[32][66];  // [token][2k] duplicated q pairs (+pad)
    __shared__ float ks[32][256];  // [k][key] transposed

    const int tid = threadIdx.x;
    const int tx = tid & 31;
    const int wy = tid >> 5;       // warp id: token group
    const int tt = blockIdx.x;
    const int h = blockIdx.y;
    const int t0 = tt * 32;

    const int tl = tid >> 3;
    const int kc = (tid & 7) << 2;

    float s1s0[4], s1s1[4];        // stage-1 results per token per p
    int   s1i0[4], s1i1[4];

#pragma unroll 1
    for (int p = 0; p < 2; p++) {
        ull acc[4][4];             // [token][key-quad] — reused across p
#pragma unroll
        for (int i = 0; i < 4; i++)
#pragma unroll
            for (int jq = 0; jq < 4; jq++) acc[i][jq] = 0ULL;

        const float* qb = g_q + (size_t)(p * HV + h) * DHV;
        const float* kb = keys + ((size_t)(h * NKV + tid) * 2 + p) * DHV;
        for (int kt = 0; kt < DHV; kt += 32) {
            __syncthreads();
            float4 q4 = *(const float4*)(qb + (size_t)(t0 + tl) * QDV + kt + kc);
            *(float2*)&qsd[tl][2 * (kc + 0)] = make_float2(q4.x, q4.x);
            *(float2*)&qsd[tl][2 * (kc + 1)] = make_float2(q4.y, q4.y);
            *(float2*)&qsd[tl][2 * (kc + 2)] = make_float2(q4.z, q4.z);
            *(float2*)&qsd[tl][2 * (kc + 3)] = make_float2(q4.w, q4.w);
            const float* kr = kb + kt;  // key row n = tid (256 keys)
#pragma unroll
            for (int c = 0; c < 8; c++) {
                float4 k4 = *(const float4*)(kr + c * 4);
                ks[c * 4 + 0][tid] = k4.x; ks[c * 4 + 1][tid] = k4.y;
                ks[c * 4 + 2][tid] = k4.z; ks[c * 4 + 3][tid] = k4.w;
            }
            __syncthreads();
#pragma unroll 4
            for (int k = 0; k < 32; k++) {
                ulonglong2 kq0 = *(const ulonglong2*)&ks[k][4 * tx];
                ulonglong2 kq1 = *(const ulonglong2*)&ks[k][128 + 4 * tx];
                ull kv[4] = {kq0.x, kq0.y, kq1.x, kq1.y};
#pragma unroll
                for (int i = 0; i < 4; i++) {
                    ull qd = *(const ull*)&qsd[wy + 8 * i][2 * k];
#pragma unroll
                    for (int jq = 0; jq < 4; jq++)
                        FMA2(acc[i][jq], qd, kv[jq]);
                }
            }
        }

        // stage-1 for this p: top-16 of 256 per token, ALL 4 tokens ILP.
        // slot s holds key n(s) = (s>=4)*128 + 4*tx + (s&3) — increasing in s.
        float v[4][8];
#pragma unroll
        for (int i = 0; i < 4; i++)
#pragma unroll
            for (int jq = 0; jq < 4; jq++) {
                unsigned lo, hi;
                UNPACK2(lo, hi, acc[i][jq]);
                v[i][2 * jq + 0] = __uint_as_float(lo);
                v[i][2 * jq + 1] = __uint_as_float(hi);
            }
        float osr[4]; int oir[4];
#pragma unroll
        for (int i = 0; i < 4; i++) { osr[i] = 0.f; oir[i] = 0; }
#pragma unroll 1
        for (int it = 0; it < 16; it++) {
            float bv[4]; int bi[4];
#pragma unroll
            for (int i = 0; i < 4; i++) { bv[i] = -INFINITY; bi[i] = 0x7fffffff; }
#pragma unroll
            for (int s = 0; s < 8; s++) {
                int n = ((s >> 2) << 7) + 4 * tx + (s & 3);
#pragma unroll
                for (int i = 0; i < 4; i++)
                    if (v[i][s] > bv[i]) { bv[i] = v[i][s]; bi[i] = n; }
            }
#pragma unroll
            for (int o = 16; o; o >>= 1) {
#pragma unroll
                for (int i = 0; i < 4; i++) {
                    float ov = __shfl_xor_sync(0xffffffffu, bv[i], o);
                    int   on = __shfl_xor_sync(0xffffffffu, bi[i], o);
                    if (ov > bv[i] || (ov == bv[i] && on < bi[i])) { bv[i] = ov; bi[i] = on; }
                }
            }
#pragma unroll
            for (int i = 0; i < 4; i++) {
                if (tx == it) { osr[i] = bv[i]; oir[i] = bi[i]; }
                if (((bi[i] >> 2) & 31) == tx) {
                    int sl = ((bi[i] >> 7) << 2) | (bi[i] & 3);
                    v[i][sl] = -INFINITY;
                }
            }
        }
#pragma unroll
        for (int i = 0; i < 4; i++) {
            if (p == 0) { s1s0[i] = osr[i]; s1i0[i] = oir[i]; }
            else        { s1s1[i] = osr[i]; s1i1[i] = oir[i]; }
        }
    }

    // stage-2: top-16 of 50 pruned candidates, ALL 4 tokens ILP.
    float v2[4][2];
    int cc2[2];                    // candidate ids identical for all tokens
#pragma unroll
    for (int e = 0; e < 2; e++) {
        int c = tx + 32 * e;
        int ii = c_ci[c], jj = c_cj[c];
        cc2[e] = ii * 16 + jj;
#pragma unroll
        for (int i = 0; i < 4; i++) {
            float sxv = __shfl_sync(0xffffffffu, s1s0[i], ii);
            float syv = __shfl_sync(0xffffffffu, s1s1[i], jj);
            v2[i][e] = (c < 50) ? sxv + syv : -INFINITY;
        }
    }
    float os[4]; int occ[4];
#pragma unroll
    for (int i = 0; i < 4; i++) { os[i] = 0.f; occ[i] = 0; }
#pragma unroll 1
    for (int it = 0; it < 16; it++) {
        float bv[4]; int bcc[4];
#pragma unroll
        for (int i = 0; i < 4; i++) { bv[i] = -INFINITY; bcc[i] = 0x7fffffff; }
#pragma unroll
        for (int e = 0; e < 2; e++)
#pragma unroll
            for (int i = 0; i < 4; i++)
                if (v2[i][e] > bv[i] || (v2[i][e] == bv[i] && cc2[e] < bcc[i])) {
                    bv[i] = v2[i][e]; bcc[i] = cc2[e];
                }
#pragma unroll
        for (int o = 16; o; o >>= 1) {
#pragma unroll
            for (int i = 0; i < 4; i++) {
                float ov = __shfl_xor_sync(0xffffffffu, bv[i], o);
                int   oc = __shfl_xor_sync(0xffffffffu, bcc[i], o);
                if (ov > bv[i] || (ov == bv[i] && oc < bcc[i])) { bv[i] = ov; bcc[i] = oc; }
            }
        }
#pragma unroll
        for (int i = 0; i < 4; i++) {
            if (tx == it) { os[i] = bv[i]; occ[i] = bcc[i]; }
#pragma unroll
            for (int e = 0; e < 2; e++)
                if (cc2[e] == bcc[i]) v2[i][e] = -INFINITY;
        }
    }

    // softmax over 16 selected (lane 0 = max) + index gather, ILP-4.
    float ev[4], sum[4];
#pragma unroll
    for (int i = 0; i < 4; i++) {
        float mx = __shfl_sync(0xffffffffu, os[i], 0);
        ev[i] = (tx < 16) ? expf(os[i] - mx) : 0.f;
        sum[i] = ev[i];
    }
#pragma unroll
    for (int o = 16; o; o >>= 1)
#pragma unroll
        for (int i = 0; i < 4; i++)
            sum[i] += __shfl_xor_sync(0xffffffffu, sum[i], o);
#pragma unroll
    for (int i = 0; i < 4; i++) {
        int ix = __shfl_sync(0xffffffffu, s1i0[i], (occ[i] >> 4) & 15);
        int iy = __shfl_sync(0xffffffffu, s1i1[i], occ[i] & 15);
        if (tx < 16) {
            const int t = t0 + wy + 8 * i;
            int o = (t * HV + h) * KKV + tx;
            g_attn[o] = ev[i] / sum[i];
            g_vidx[o] = ix * NKV + iy;
        }
    }
}

// ---------------------------------------------------------------------------
// K5: out[t,:] = sum_{m<128} attn[t,m] * values[vidx[t,m], :]
// (at DRAM/L2 bandwidth floor per ncu — unchanged)
// ---------------------------------------------------------------------------
__global__ __launch_bounds__(128) void k5_out(const float* __restrict__ values,
                                              float* __restrict__ out)
{
    __shared__ float sa[128];
    __shared__ int   sv[128];
    const int t = blockIdx.x;
    const int tid = threadIdx.x;
    sa[tid] = g_attn[(size_t)t * 128 + tid];
    sv[tid] = g_vidx[(size_t)t * 128 + tid];
    __syncthreads();

    const float4* V = (const float4*)values;
    float4 acc = make_float4(0.f, 0.f, 0.f, 0.f);
#pragma unroll 8
    for (int m = 0; m < 128; m++) {
        float a = sa[m];
        float4 vv = V[(size_t)sv[m] * 128 + tid];
        acc.x = fmaf(a, vv.x, acc.x);
        acc.y = fmaf(a, vv.y, acc.y);
        acc.z = fmaf(a, vv.z, acc.z);
        acc.w = fmaf(a, vv.w, acc.w);
    }
    ((float4*)out)[(size_t)t * 128 + tid] = acc;
}

// ---------------------------------------------------------------------------
extern "C" void kernel_launch(void* const* d_in, const int* in_sizes, int n_in,
                              void* d_out, int out_size)
{
    const float* x      = (const float*)d_in[0];  // (4,1024,512)
    const float* Wq     = (const float*)d_in[1];  // (2048,512)
    const float* ln_g   = (const float*)d_in[2];  // (128,)
    const float* ln_b   = (const float*)d_in[3];  // (128,)
    const float* keys   = (const float*)d_in[4];  // (8,256,2,128)
    const float* values = (const float*)d_in[5];  // (65536,512)
    float* out = (float*)d_out;                   // (4,1024,512)

    k1_gemm_ln<<<dim3(NTOKS / 64, QDV / 128), 256>>>(x, Wq, ln_g, ln_b);
    k3_fused<<<dim3(NTOKS / 32, HV), 256>>>(keys);
    k5_out<<<NTOKS, 128>>>(values, out);
}